// round 12
// baseline (speedup 1.0000x reference)
#include <cuda_runtime.h>

// Fused depthwise conv: y = gauss_valid(fd_valid(x)) == one 13-tap valid FIR.
// Composed kernel is SYMMETRIC: out[j] = sum_{k<6} w[k]*(x[j+k]+x[j+12-k])
//                                        + w[6]*x[j+6].
//
// x: [8,4,T] f32 -> 32 rows, T = 1048576. out rows: Tout = T-12.
//
// R10: R8 structure (persistent, 6 CTAs/SM, GROUPS=2 coalesced LDG.128,
// int32 + shift/mask addressing, symmetric weights) + L2 PREFETCH of the
// next grid-stride tile. Prefetches carry no register dependency, so the
// DRAM fill stream is decoupled from the 40-reg MLP limit; next iteration's
// demand loads hit L2 (~250cyc) instead of DRAM (~600cyc).

#define BLOCK  256
#define GROUPS 2
#define GTILE  (BLOCK * 4)        // 1024 outputs per group
#define TILE   (GTILE * GROUPS)   // 2048 outputs per tile = 8KB = 64 lines
#define TPR_LOG2 9                // tilesPerRow = 512 (for T=2^20)

__global__ __launch_bounds__(BLOCK, 6)
void fused_fir13_pf(const float* __restrict__ x,
                    const float* __restrict__ fd,   // 5 taps
                    const float* __restrict__ gk,   // 9 taps
                    float* __restrict__ out,
                    int T, int Tout, int tilesTotal)
{
    __shared__ float wsh[7];
    const int tid = threadIdx.x;

    // Compose symmetric half-kernel once per CTA.
    if (tid < 7) {
        float acc = 0.f;
        const int hi = tid < 4 ? tid : 4;
        for (int i = 0; i <= hi; ++i) acc += fd[i] * gk[tid - i];
        wsh[tid] = acc;
    }
    __syncthreads();

    float w[7];
    #pragma unroll
    for (int k = 0; k < 7; ++k) w[k] = wsh[k];

    const int step = gridDim.x;

    for (int t = blockIdx.x; t < tilesTotal; t += step) {
        const int row  = t >> TPR_LOG2;                 // block-uniform
        const int tile = t & ((1 << TPR_LOG2) - 1);
        const int xb   = row * T;                       // int32 (max ~33.5M)
        const int ob   = row * Tout;
        const int start = tile * TILE;

        // ---- Front-batch demand loads: coalesced LDG.128 ----
        float r[GROUPS][16];
        #pragma unroll
        for (int q = 0; q < GROUPS; ++q) {
            const int gb = start + q * GTILE + tid * 4;
            if (gb + 16 <= T) {
                #pragma unroll
                for (int v = 0; v < 4; ++v) {
                    float4 f = *(const float4*)(x + xb + gb + 4 * v);
                    r[q][4*v+0] = f.x; r[q][4*v+1] = f.y;
                    r[q][4*v+2] = f.z; r[q][4*v+3] = f.w;
                }
            } else {
                #pragma unroll
                for (int i = 0; i < 16; ++i) {
                    const int gi = gb + i;
                    r[q][i] = (gi < T) ? x[xb + gi] : 0.f;
                }
            }
        }

        // ---- L2-prefetch next tile (64 lines; threads 0..63, 1 line each).
        //      No destination regs, no dependents: pure pipelined DRAM fill.
        {
            const int tn = t + step;
            if (tn < tilesTotal && tid < 64) {
                const int rown  = tn >> TPR_LOG2;
                const int tilen = tn & ((1 << TPR_LOG2) - 1);
                const float* p = x + rown * T + tilen * TILE + tid * 32;
                asm volatile("prefetch.global.L2 [%0];" :: "l"(p));
            }
        }

        // ---- Compute + store per group ----
        #pragma unroll
        for (int q = 0; q < GROUPS; ++q) {
            const int gb = start + q * GTILE + tid * 4;
            float a[4];
            #pragma unroll
            for (int j = 0; j < 4; ++j) {
                float acc = w[6] * r[q][j + 6];
                #pragma unroll
                for (int k = 0; k < 6; ++k)
                    acc = fmaf(w[k], r[q][j + k] + r[q][j + 12 - k], acc);
                a[j] = acc;
            }
            if (gb + 4 <= Tout) {
                *(float4*)(out + ob + gb) = make_float4(a[0], a[1], a[2], a[3]);
            } else {
                #pragma unroll
                for (int v = 0; v < 4; ++v)
                    if (gb + v < Tout) out[ob + gb + v] = a[v];
            }
        }
    }
}

extern "C" void kernel_launch(void* const* d_in, const int* in_sizes, int n_in,
                              void* d_out, int out_size)
{
    const float* x  = (const float*)d_in[0];
    const float* fd = (const float*)d_in[1];   // 5 elements
    const float* gk = (const float*)d_in[2];   // 9 elements
    float* out = (float*)d_out;

    const int ROWS = 32;                       // 8 * 4
    const int T    = in_sizes[0] / ROWS;       // 1048576
    const int Tout = T - 12;                   // 1048564

    const int tilesPerRow = 1 << TPR_LOG2;              // 512
    const int tilesTotal  = ROWS * tilesPerRow;         // 16384

    const int SMS = 148, CTAS_PER_SM = 6;
    int blocks = SMS * CTAS_PER_SM;                     // 888 persistent CTAs
    if (blocks > tilesTotal) blocks = tilesTotal;

    fused_fir13_pf<<<blocks, BLOCK>>>(x, fd, gk, out, T, Tout, tilesTotal);
}